// round 10
// baseline (speedup 1.0000x reference)
#include <cuda_runtime.h>
#include <cuda_fp16.h>
#include <cstdint>

#define NT    16384
#define DIM   2048
#define NE    64
#define TT    128
#define KCH   128
#define NCHK  16
#define LSTR  66
#define GAP_THRESH 1e-4f

// per-buf smem: XH 32K | XM 32K | WH 16K | WM 16K  = 96K; 2 bufs = 192K
#define XH    0
#define XM    32768
#define WH    65536
#define WM    81920
#define BUFB  98304
#define SMEM_TOTAL (2 * BUFB)

// w fp16 planes, chunk-ordered, pre-swizzled: [ch(16)] { h: 64x256B, m: 64x256B }
__device__ __align__(16) unsigned char g_w[NCHK * 32768];   // 512 KB

__device__ __forceinline__ uint32_t smem_u32(const void* p) {
    uint32_t a;
    asm("{ .reg .u64 t; cvta.to.shared.u64 t, %1; cvt.u32.u64 %0, t; }" : "=r"(a) : "l"(p));
    return a;
}
__device__ __forceinline__ void split2(float a, float b, uint32_t& h, uint32_t& m) {
    __half2 hh = __floats2half2_rn(a, b);
    float2 hf = __half22float2(hh);
    __half2 mm = __floats2half2_rn(a - hf.x, b - hf.y);
    h = *reinterpret_cast<uint32_t*>(&hh);
    m = *reinterpret_cast<uint32_t*>(&mm);
}
__device__ __forceinline__ void ldm4(uint32_t addr, uint32_t& r0, uint32_t& r1,
                                     uint32_t& r2, uint32_t& r3) {
    asm volatile("ldmatrix.sync.aligned.m8n8.x4.shared.b16 {%0,%1,%2,%3}, [%4];"
                 : "=r"(r0), "=r"(r1), "=r"(r2), "=r"(r3) : "r"(addr));
}
__device__ __forceinline__ void mma16816(float* c, const uint32_t* a,
                                         uint32_t b0, uint32_t b1) {
    asm volatile("mma.sync.aligned.m16n8k16.row.col.f32.f16.f16.f32 "
                 "{%0,%1,%2,%3}, {%4,%5,%6,%7}, {%8,%9}, {%0,%1,%2,%3};"
                 : "+f"(c[0]), "+f"(c[1]), "+f"(c[2]), "+f"(c[3])
                 : "r"(a[0]), "r"(a[1]), "r"(a[2]), "r"(a[3]), "r"(b0), "r"(b1));
}
#define CP16(sa, ga) \
    asm volatile("cp.async.ca.shared.global [%0], [%1], 16;" :: "r"(sa), "l"(ga))
#define CP_COMMIT() asm volatile("cp.async.commit_group;" ::: "memory")
#define CP_WAIT0()  asm volatile("cp.async.wait_group 0;" ::: "memory")

// ---- prep: w (x256) -> fp16 h/m planes, chunk-ordered + swizzled ----
__global__ __launch_bounds__(256) void prep_wf(const float* __restrict__ w) {
    const int idx = blockIdx.x * 256 + threadIdx.x;     // 16384 = 64e x 256 k8
    const int e = idx >> 8;
    const int k = (idx & 255) * 8;
    float4 v0 = *reinterpret_cast<const float4*>(w + (size_t)e * DIM + k);
    float4 v1 = *reinterpret_cast<const float4*>(w + (size_t)e * DIM + k + 4);
    uint32_t h[4], m[4];
    split2(v0.x * 256.0f, v0.y * 256.0f, h[0], m[0]);
    split2(v0.z * 256.0f, v0.w * 256.0f, h[1], m[1]);
    split2(v1.x * 256.0f, v1.y * 256.0f, h[2], m[2]);
    split2(v1.z * 256.0f, v1.w * 256.0f, h[3], m[3]);
    const int ch = k >> 7, c = (k & 127) >> 3;          // chunk, 16B-col within row
    const uint32_t off = (uint32_t)(e * 256 + ((c ^ (e & 7)) << 4));
    *reinterpret_cast<uint4*>(g_w + (size_t)ch * 32768 + off)         = make_uint4(h[0], h[1], h[2], h[3]);
    *reinterpret_cast<uint4*>(g_w + (size_t)ch * 32768 + 16384 + off) = make_uint4(m[0], m[1], m[2], m[3]);
}

// ---- main ----
__global__ __launch_bounds__(512, 1)
void router_hmma(const float* __restrict__ x, const float* __restrict__ w,
                 float* __restrict__ out)
{
    extern __shared__ __align__(1024) char smem[];
    const uint32_t sb = smem_u32(smem);

    __shared__ int   s_cnt;
    __shared__ int   s_list[TT];
    __shared__ float s_part[8][64];
    __shared__ float s_lg[66];

    const int tid  = threadIdx.x;
    const int lane = tid & 31;
    const int wp   = tid >> 5;       // 0..15
    const int tg   = wp & 7;         // token group x16
    const int eh   = wp >> 3;        // expert half x32
    const int tok0 = blockIdx.x * TT;

    if (tid == 0) s_cnt = 0;

    // x loader: row = tid>>2 (128 rows), 32 k per thread
    const int xrow = tid >> 2, xq = tid & 3;
    const float* xg = x + (size_t)(tok0 + xrow) * DIM + xq * 32;
    uint32_t xst[4];
#pragma unroll
    for (int j = 0; j < 4; j++)
        xst[j] = (uint32_t)(xrow * 256 + (((xq * 4 + j) ^ (xrow & 7)) << 4));

    float4 rx[8];
    auto loadX = [&](int ch) {
#pragma unroll
        for (int i = 0; i < 8; i++)
            rx[i] = *reinterpret_cast<const float4*>(xg + ch * KCH + i * 4);
    };
    auto convX = [&](int b) {
        char* xb = smem + b * BUFB;
#pragma unroll
        for (int j = 0; j < 4; j++) {
            uint32_t h[4], m[4];
            split2(rx[2 * j].x,     rx[2 * j].y,     h[0], m[0]);
            split2(rx[2 * j].z,     rx[2 * j].w,     h[1], m[1]);
            split2(rx[2 * j + 1].x, rx[2 * j + 1].y, h[2], m[2]);
            split2(rx[2 * j + 1].z, rx[2 * j + 1].w, h[3], m[3]);
            *reinterpret_cast<uint4*>(xb + XH + xst[j]) = make_uint4(h[0], h[1], h[2], h[3]);
            *reinterpret_cast<uint4*>(xb + XM + xst[j]) = make_uint4(m[0], m[1], m[2], m[3]);
        }
    };
    auto issueW = [&](int ch, int b) {
        const unsigned char* src = g_w + (size_t)ch * 32768;
#pragma unroll
        for (int it = 0; it < 4; it++) {
            int i = tid + 512 * it;                 // 0..2047 x 16B = 32KB
            CP16(sb + b * BUFB + WH + i * 16, src + i * 16);
        }
    };

    // ldmatrix lane addressing
    const int l7 = lane & 7, gA = (lane >> 3) & 1, gB = lane >> 4;
    const uint32_t aRow  = (uint32_t)((tg * 16 + l7 + gA * 8) * 256);
    const uint32_t bRow0 = (uint32_t)((eh * 32 + l7 + gB * 8) * 256);
    const uint32_t bRow1 = bRow0 + 16 * 256;

    float acc[4][4];
#pragma unroll
    for (int j = 0; j < 4; j++)
#pragma unroll
        for (int q = 0; q < 4; q++) acc[j][q] = 0.0f;

    // prologue: stage chunk 0
    issueW(0, 0);
    CP_COMMIT();
    loadX(0);
    convX(0);

    for (int ch = 0; ch < NCHK; ch++) {
        const int b = ch & 1;
        CP_WAIT0();
        __syncthreads();    // buf b fully staged; everyone done with buf b^1

        if (ch + 1 < NCHK) {
            issueW(ch + 1, b ^ 1);
            CP_COMMIT();
            loadX(ch + 1);   // LDG in flight across this chunk's compute
        }

        const uint32_t xhb = sb + (uint32_t)(b * BUFB) + XH + aRow;
        const uint32_t whb0 = sb + (uint32_t)(b * BUFB) + WH + bRow0;
        const uint32_t whb1 = sb + (uint32_t)(b * BUFB) + WH + bRow1;
#pragma unroll
        for (int s = 0; s < 8; s++) {
            const uint32_t csA = (uint32_t)(((2 * s + gB) ^ l7) << 4);
            const uint32_t csB = (uint32_t)(((2 * s + gA) ^ l7) << 4);
            uint32_t ah[4], am[4], bh[8], bm[8];
            ldm4(xhb + csA, ah[0], ah[1], ah[2], ah[3]);
            ldm4(xhb + (XM - XH) + csA, am[0], am[1], am[2], am[3]);
            ldm4(whb0 + csB, bh[0], bh[1], bh[2], bh[3]);
            ldm4(whb1 + csB, bh[4], bh[5], bh[6], bh[7]);
#pragma unroll
            for (int j = 0; j < 4; j++) mma16816(acc[j], ah, bh[2 * j], bh[2 * j + 1]);
#pragma unroll
            for (int j = 0; j < 4; j++) mma16816(acc[j], am, bh[2 * j], bh[2 * j + 1]);
            ldm4(whb0 + (WM - WH) + csB, bm[0], bm[1], bm[2], bm[3]);
            ldm4(whb1 + (WM - WH) + csB, bm[4], bm[5], bm[6], bm[7]);
#pragma unroll
            for (int j = 0; j < 4; j++) mma16816(acc[j], ah, bm[2 * j], bm[2 * j + 1]);
        }
        if (ch + 1 < NCHK) convX(b ^ 1);   // writes buf b^1 (no reader until next sync)
    }

    __syncthreads();
    // ---- logits -> smem (undo x256 w scale); reuses buf0 area (last compute was buf1) ----
    float* ls = reinterpret_cast<float*>(smem);
    {
        const int qrow = lane >> 2, qk = (lane & 3) * 2;
        const int r0 = tg * 16 + qrow, r1 = r0 + 8;
        const int e00 = eh * 32 + qk;
#pragma unroll
        for (int j = 0; j < 4; j++) {
            int e = e00 + 8 * j;
            *reinterpret_cast<float2*>(ls + r0 * LSTR + e) =
                make_float2(acc[j][0] * 0.00390625f, acc[j][1] * 0.00390625f);
            *reinterpret_cast<float2*>(ls + r1 * LSTR + e) =
                make_float2(acc[j][2] * 0.00390625f, acc[j][3] * 0.00390625f);
        }
    }
    __syncthreads();

    float* outp = out;
    float* outi = out + (size_t)NT * 8;
    float* outa = out + (size_t)NT * 16;

    const int tbase = wp * 8;
#pragma unroll 1
    for (int tt = 0; tt < 8; tt++) {
        const int tok = tbase + tt;
        float2 v = *reinterpret_cast<const float2*>(ls + tok * LSTR + 2 * lane);

        float m = fmaxf(v.x, v.y);
#pragma unroll
        for (int o = 16; o > 0; o >>= 1)
            m = fmaxf(m, __shfl_xor_sync(0xffffffffu, m, o));

        float e0 = expf(v.x - m);
        float e1 = expf(v.y - m);
        float ssum = e0 + e1;
#pragma unroll
        for (int o = 16; o > 0; o >>= 1)
            ssum += __shfl_xor_sync(0xffffffffu, ssum, o);

        float inv = 1.0f / ssum;
        float p0 = e0 * inv, p1 = e1 * inv;

        const int gtok = tok0 + tok;
        *reinterpret_cast<float2*>(outa + (size_t)gtok * 64 + 2 * lane)
            = make_float2(p0, p1);

        // top-9 on logits, min adjacent gap -> flag near-ties
        float c0 = v.x, c1 = v.y;
        int i0 = 2 * lane, i1 = 2 * lane + 1;
        float tv = 0.0f, tsum = 0.0f, prevv = 0.0f, mingap = 1e30f;
        int ti = 0;
#pragma unroll
        for (int r = 0; r < 9; r++) {
            float bv; int bi;
            if (c0 > c1 || (c0 == c1 && i0 < i1)) { bv = c0; bi = i0; }
            else                                  { bv = c1; bi = i1; }
#pragma unroll
            for (int o = 16; o > 0; o >>= 1) {
                float ov = __shfl_xor_sync(0xffffffffu, bv, o);
                int   oi = __shfl_xor_sync(0xffffffffu, bi, o);
                if (ov > bv || (ov == bv && oi < bi)) { bv = ov; bi = oi; }
            }
            if (r > 0) mingap = fminf(mingap, prevv - bv);
            prevv = bv;
            if (r < 8) {
                float bp = expf(bv - m) * inv;
                tsum += bp;
                if (lane == r) { tv = bp; ti = bi; }
                if (bi == i0)      c0 = -1e30f;
                else if (bi == i1) c1 = -1e30f;
            }
        }
        if (lane < 8) {
            outp[(size_t)gtok * 8 + lane] = tv / (tsum + 1e-9f);
            outi[(size_t)gtok * 8 + lane] = (float)ti;
        }
        if (lane == 0 && mingap < GAP_THRESH) {
            int pos = atomicAdd(&s_cnt, 1);
            s_list[pos] = gtok;
        }
    }

    // ---- inline exact fp32 fixup ----
    __syncthreads();
    const int nfix = s_cnt;
    for (int i = 0; i < nfix; i++) {
        const int tok = s_list[i];
        const int e = tid & 63, kp = tid >> 6;        // 8 k-parts of 256
        const float* xr = x + (size_t)tok * DIM + kp * 256;
        const float* wr = w + (size_t)e * DIM + kp * 256;
        float s = 0.0f;
#pragma unroll 4
        for (int k = 0; k < 256; k += 4) {
            float4 xv = *reinterpret_cast<const float4*>(xr + k);
            float4 wv = *reinterpret_cast<const float4*>(wr + k);
            s = fmaf(xv.x, wv.x, s);
            s = fmaf(xv.y, wv.y, s);
            s = fmaf(xv.z, wv.z, s);
            s = fmaf(xv.w, wv.w, s);
        }
        s_part[kp][e] = s;
        __syncthreads();
        if (tid < 64) {
            float a = (s_part[0][tid] + s_part[1][tid]) + (s_part[2][tid] + s_part[3][tid]);
            float b = (s_part[4][tid] + s_part[5][tid]) + (s_part[6][tid] + s_part[7][tid]);
            s_lg[tid] = a + b;
        }
        __syncthreads();

        if (tid < 32) {
            float2 v = make_float2(s_lg[2 * lane], s_lg[2 * lane + 1]);

            float m = fmaxf(v.x, v.y);
#pragma unroll
            for (int o = 16; o > 0; o >>= 1)
                m = fmaxf(m, __shfl_xor_sync(0xffffffffu, m, o));

            float e0 = expf(v.x - m);
            float e1 = expf(v.y - m);
            float ssum = e0 + e1;
#pragma unroll
            for (int o = 16; o > 0; o >>= 1)
                ssum += __shfl_xor_sync(0xffffffffu, ssum, o);

            float inv = 1.0f / ssum;
            float p0 = e0 * inv, p1 = e1 * inv;

            *reinterpret_cast<float2*>(outa + (size_t)tok * 64 + 2 * lane)
                = make_float2(p0, p1);

            float c0 = p0, c1 = p1;
            int i0 = 2 * lane, i1 = 2 * lane + 1;
            float tv = 0.0f, tsum = 0.0f;
            int ti = 0;
#pragma unroll
            for (int r = 0; r < 8; r++) {
                float bv; int bi;
                if (c0 > c1 || (c0 == c1 && i0 < i1)) { bv = c0; bi = i0; }
                else                                  { bv = c1; bi = i1; }
#pragma unroll
                for (int o = 16; o > 0; o >>= 1) {
                    float ov = __shfl_xor_sync(0xffffffffu, bv, o);
                    int   oi = __shfl_xor_sync(0xffffffffu, bi, o);
                    if (ov > bv || (ov == bv && oi < bi)) { bv = ov; bi = oi; }
                }
                tsum += bv;
                if (lane == r) { tv = bv; ti = bi; }
                if (bi == i0)      c0 = -1.0f;
                else if (bi == i1) c1 = -1.0f;
            }
            if (lane < 8) {
                outp[(size_t)tok * 8 + lane] = tv / (tsum + 1e-9f);
                outi[(size_t)tok * 8 + lane] = (float)ti;
            }
        }
        __syncthreads();
    }
}

extern "C" void kernel_launch(void* const* d_in, const int* in_sizes, int n_in,
                              void* d_out, int out_size)
{
    (void)in_sizes; (void)n_in; (void)out_size;
    const float* x = (const float*)d_in[0];
    const float* w = (const float*)d_in[1];
    cudaFuncSetAttribute(router_hmma, cudaFuncAttributeMaxDynamicSharedMemorySize,
                         SMEM_TOTAL);
    prep_wf<<<64, 256>>>(w);
    router_hmma<<<NT / TT, 512, SMEM_TOTAL>>>(x, w, (float*)d_out);
}